// round 2
// baseline (speedup 1.0000x reference)
#include <cuda_runtime.h>
#include <math.h>

#define NN 100000
#define EE 1600000
#define DD 128
#define LL 3
#define EPSV 1e-5f
#define NCH ((NN + 1023) / 1024)   // scan chunks = 98

// ---------------- scratch (static __device__, no allocation) ----------------
__device__ int   g_is64;
__device__ int   g_src[EE];
__device__ int   g_dst[EE];
__device__ int   g_deg[NN];
__device__ int   g_rowptr[NN + 1];
__device__ int   g_cursor[NN];
__device__ int   g_col[EE];
__device__ int   g_bsum[128];
__device__ int   g_boff[128];
__device__ float g_invdeg[NN];
__device__ float g_h[NN * DD];      // BN output (layer input for l>0)
__device__ float g_mean[NN * DD];   // aggregated neighbor mean
__device__ float g_tmp[NN * DD];    // relu(sage) pre-BN
__device__ float g_sum[DD];
__device__ float g_sumsq[DD];
__device__ float g_scale[DD];
__device__ float g_shift[DD];
__device__ float g_p[NN];
__device__ float g_q[NN];

// ---------------- dtype detect + edge conversion ----------------
// If edge_index is int64 (values < 2^17), every odd 32-bit word is 0.
// If int32, odd words are random node indices -> virtually never all zero.
__global__ void k_detect(const unsigned int* __restrict__ w) {
    __shared__ int nz;
    if (threadIdx.x == 0) nz = 0;
    __syncthreads();
    if (w[threadIdx.x * 2 + 1] != 0u) atomicOr(&nz, 1);
    __syncthreads();
    if (threadIdx.x == 0) g_is64 = nz ? 0 : 1;
}

__global__ void k_convert(const void* __restrict__ ei) {
    int e = blockIdx.x * blockDim.x + threadIdx.x;
    if (e >= EE) return;
    int s, d;
    if (g_is64) {
        const long long* p = (const long long*)ei;
        s = (int)p[e];
        d = (int)p[EE + e];
    } else {
        const int* p = (const int*)ei;
        s = p[e];
        d = p[EE + e];
    }
    s = min(max(s, 0), NN - 1);
    d = min(max(d, 0), NN - 1);
    g_src[e] = s;
    g_dst[e] = d;
}

// ---------------- CSR build ----------------
__global__ void k_zero_deg() {
    int i = blockIdx.x * blockDim.x + threadIdx.x;
    if (i < NN) g_deg[i] = 0;
}

__global__ void k_hist() {
    int e = blockIdx.x * blockDim.x + threadIdx.x;
    if (e < EE) atomicAdd(&g_deg[g_dst[e]], 1);
}

__global__ void k_scan_a() {
    __shared__ int swarp[32];
    int tid = threadIdx.x;
    int i = blockIdx.x * 1024 + tid;
    int v = (i < NN) ? g_deg[i] : 0;
    int lane = tid & 31, w = tid >> 5;
    int x = v;
    #pragma unroll
    for (int o = 1; o < 32; o <<= 1) {
        int y = __shfl_up_sync(0xffffffffu, x, o);
        if (lane >= o) x += y;
    }
    if (lane == 31) swarp[w] = x;
    __syncthreads();
    if (w == 0) {
        int y = swarp[lane];
        #pragma unroll
        for (int o = 1; o < 32; o <<= 1) {
            int z = __shfl_up_sync(0xffffffffu, y, o);
            if (lane >= o) y += z;
        }
        swarp[lane] = y;
    }
    __syncthreads();
    int add = (w > 0) ? swarp[w - 1] : 0;
    x += add;
    if (i < NN) g_rowptr[i + 1] = x;                 // inclusive within chunk
    if (tid == 1023) g_bsum[blockIdx.x] = x;         // chunk total
}

__global__ void k_scan_b() {
    if (threadIdx.x == 0) {
        int r = 0;
        for (int b = 0; b < NCH; b++) { g_boff[b] = r; r += g_bsum[b]; }
    }
}

__global__ void k_scan_c() {
    int i = blockIdx.x * blockDim.x + threadIdx.x;
    if (i < NN) {
        g_rowptr[i + 1] += g_boff[i >> 10];
        if (i == 0) g_rowptr[0] = 0;
    }
}

__global__ void k_prep() {
    int i = blockIdx.x * blockDim.x + threadIdx.x;
    if (i < NN) {
        g_cursor[i] = g_rowptr[i];
        int d = g_deg[i];
        g_invdeg[i] = (d > 0) ? (1.0f / (float)d) : 0.0f;
    }
}

__global__ void k_scatter() {
    int e = blockIdx.x * blockDim.x + threadIdx.x;
    if (e < EE) {
        int pos = atomicAdd(&g_cursor[g_dst[e]], 1);
        g_col[pos] = g_src[e];
    }
}

// ---------------- aggregation: mean over in-neighbors ----------------
// One block (128 threads) per node; thread = feature column. Coalesced 512B
// row reads; working set (51 MB) is L2-resident.
__global__ void k_agg(const float* __restrict__ x, int firstLayer) {
    const float* __restrict__ in = firstLayer ? x : g_h;
    int n = blockIdx.x;
    int c = threadIdx.x;
    int s = g_rowptr[n], e = g_rowptr[n + 1];
    float acc = 0.0f;
    int j = s;
    for (; j + 3 < e; j += 4) {
        int c0 = g_col[j], c1 = g_col[j + 1], c2 = g_col[j + 2], c3 = g_col[j + 3];
        float a = __ldg(&in[c0 * DD + c]);
        float b = __ldg(&in[c1 * DD + c]);
        float cc = __ldg(&in[c2 * DD + c]);
        float d = __ldg(&in[c3 * DD + c]);
        acc += a + b + cc + d;
    }
    for (; j < e; j++) acc += __ldg(&in[g_col[j] * DD + c]);
    g_mean[n * DD + c] = acc * g_invdeg[n];
}

// ---------------- stats ----------------
__global__ void k_zero_stats() {
    int c = threadIdx.x;
    if (c < DD) { g_sum[c] = 0.0f; g_sumsq[c] = 0.0f; }
}

// ---------------- fused SAGE GEMM: out = relu(mean@Wl + root@Wr + b) ----------
// 256 threads, 64 rows/block. Both 128x128 weight matrices + both 64x128
// activation tiles in dynamic smem (192 KB). 8x4 register tile per thread.
// BN stats (col sum / sumsq) reduced in-block and atomically added globally.
__global__ void __launch_bounds__(256) k_gemm(
    const float* __restrict__ x, int firstLayer,
    const float* __restrict__ Wl, const float* __restrict__ Wr,
    const float* __restrict__ bias)
{
    extern __shared__ float sm[];
    float* sWl = sm;             // 16384 floats
    float* sWr = sm + 16384;     // 16384
    float* sA1 = sm + 32768;     // 8192  (mean tile)
    float* sA2 = sm + 40960;     // 8192  (root tile)

    const float* __restrict__ root = firstLayer ? x : g_h;
    int tid = threadIdx.x;

    // stage weights (4096 float4 each)
    for (int i = tid; i < 4096; i += 256) {
        ((float4*)sWl)[i] = ((const float4*)Wl)[i];
        ((float4*)sWr)[i] = ((const float4*)Wr)[i];
    }
    // stage activation tiles
    int rowBase = blockIdx.x * 64;
    for (int i = tid; i < 2048; i += 256) {
        int r = i >> 5;
        int kq = i & 31;
        int row = rowBase + r;
        float4 z1 = make_float4(0.f, 0.f, 0.f, 0.f);
        float4 z2 = make_float4(0.f, 0.f, 0.f, 0.f);
        if (row < NN) {
            z1 = ((const float4*)(g_mean + row * DD))[kq];
            z2 = ((const float4*)(root + row * DD))[kq];
        }
        ((float4*)(sA1 + r * DD))[kq] = z1;
        ((float4*)(sA2 + r * DD))[kq] = z2;
    }
    __syncthreads();

    int tx = tid & 31, ty = tid >> 5;
    int c0 = tx * 4;      // 4 consecutive output cols
    int r0 = ty * 8;      // 8 rows

    float acc[8][4];
    #pragma unroll
    for (int i = 0; i < 8; i++)
        #pragma unroll
        for (int jj = 0; jj < 4; jj++) acc[i][jj] = 0.0f;

    #pragma unroll 8
    for (int k = 0; k < DD; k++) {
        float4 wl = *(const float4*)(sWl + k * DD + c0);
        float4 wr = *(const float4*)(sWr + k * DD + c0);
        #pragma unroll
        for (int i = 0; i < 8; i++) {
            float a1 = sA1[(r0 + i) * DD + k];
            float a2 = sA2[(r0 + i) * DD + k];
            acc[i][0] += a1 * wl.x; acc[i][0] += a2 * wr.x;
            acc[i][1] += a1 * wl.y; acc[i][1] += a2 * wr.y;
            acc[i][2] += a1 * wl.z; acc[i][2] += a2 * wr.z;
            acc[i][3] += a1 * wl.w; acc[i][3] += a2 * wr.w;
        }
    }

    float4 bb = *(const float4*)(bias + c0);
    float cs[4] = {0.f, 0.f, 0.f, 0.f};
    float cq[4] = {0.f, 0.f, 0.f, 0.f};
    #pragma unroll
    for (int i = 0; i < 8; i++) {
        int row = rowBase + r0 + i;
        if (row < NN) {
            float v0 = fmaxf(acc[i][0] + bb.x, 0.0f);
            float v1 = fmaxf(acc[i][1] + bb.y, 0.0f);
            float v2 = fmaxf(acc[i][2] + bb.z, 0.0f);
            float v3 = fmaxf(acc[i][3] + bb.w, 0.0f);
            float4 o = make_float4(v0, v1, v2, v3);
            *(float4*)(g_tmp + row * DD + c0) = o;
            cs[0] += v0; cq[0] += v0 * v0;
            cs[1] += v1; cq[1] += v1 * v1;
            cs[2] += v2; cq[2] += v2 * v2;
            cs[3] += v3; cq[3] += v3 * v3;
        }
    }

    // block-level stats reduce (reuse smem), then one global atomic per column
    __syncthreads();
    if (tid < DD) { sm[tid] = 0.0f; sm[DD + tid] = 0.0f; }
    __syncthreads();
    #pragma unroll
    for (int jj = 0; jj < 4; jj++) {
        atomicAdd(&sm[c0 + jj], cs[jj]);
        atomicAdd(&sm[DD + c0 + jj], cq[jj]);
    }
    __syncthreads();
    if (tid < DD) {
        atomicAdd(&g_sum[tid], sm[tid]);
        atomicAdd(&g_sumsq[tid], sm[DD + tid]);
    }
}

// ---------------- BN finalize + apply ----------------
__global__ void k_bn_finalize(const float* __restrict__ gamma,
                              const float* __restrict__ beta) {
    int c = threadIdx.x;
    if (c < DD) {
        float m = g_sum[c] * (1.0f / (float)NN);
        float v = g_sumsq[c] * (1.0f / (float)NN) - m * m;
        v = fmaxf(v, 0.0f);
        float sc = gamma[c] * rsqrtf(v + EPSV);
        g_scale[c] = sc;
        g_shift[c] = beta[c] - m * sc;
    }
}

__global__ void k_bn_apply() {
    int i4 = blockIdx.x * blockDim.x + threadIdx.x;   // float4 index
    if (i4 < NN * (DD / 4)) {
        int c4 = i4 & ((DD / 4) - 1);
        float4 s  = ((const float4*)g_scale)[c4];
        float4 sh = ((const float4*)g_shift)[c4];
        float4 v  = ((const float4*)g_tmp)[i4];
        float4 o;
        o.x = s.x * v.x + sh.x;
        o.y = s.y * v.y + sh.y;
        o.z = s.z * v.z + sh.z;
        o.w = s.w * v.w + sh.w;
        ((float4*)g_h)[i4] = o;
    }
}

// ---------------- output layer: project first (linearity), then scalar agg ---
__global__ void k_pq(const float* __restrict__ wlo, const float* __restrict__ wro) {
    int warp = (blockIdx.x * blockDim.x + threadIdx.x) >> 5;
    int lane = threadIdx.x & 31;
    if (warp >= NN) return;
    float4 hv = ((const float4*)(g_h + warp * DD))[lane];
    float4 wl = ((const float4*)wlo)[lane];
    float4 wr = ((const float4*)wro)[lane];
    float p = hv.x * wl.x + hv.y * wl.y + hv.z * wl.z + hv.w * wl.w;
    float q = hv.x * wr.x + hv.y * wr.y + hv.z * wr.z + hv.w * wr.w;
    #pragma unroll
    for (int o = 16; o > 0; o >>= 1) {
        p += __shfl_down_sync(0xffffffffu, p, o);
        q += __shfl_down_sync(0xffffffffu, q, o);
    }
    if (lane == 0) { g_p[warp] = p; g_q[warp] = q; }
}

__global__ void k_final(const float* __restrict__ b_out, float* __restrict__ out) {
    int n = blockIdx.x * blockDim.x + threadIdx.x;
    if (n >= NN) return;
    int s = g_rowptr[n], e = g_rowptr[n + 1];
    float acc = 0.0f;
    for (int j = s; j < e; j++) acc += g_p[g_col[j]];
    float z = acc * g_invdeg[n] + g_q[n] + b_out[0];
    out[n] = 1.0f / (1.0f + expf(-z));
}

// ---------------- host ----------------
extern "C" void kernel_launch(void* const* d_in, const int* in_sizes, int n_in,
                              void* d_out, int out_size) {
    const float* x     = (const float*)d_in[0];
    const void*  ei    = d_in[1];
    const float* Wl    = (const float*)d_in[2];
    const float* Wr    = (const float*)d_in[3];
    const float* b     = (const float*)d_in[4];
    const float* gamma = (const float*)d_in[5];
    const float* beta  = (const float*)d_in[6];
    const float* Wlo   = (const float*)d_in[7];
    const float* Wro   = (const float*)d_in[8];
    const float* bo    = (const float*)d_in[9];
    float* out = (float*)d_out;

    const int SMEM = 196608;   // 192 KB dynamic
    cudaFuncSetAttribute(k_gemm, cudaFuncAttributeMaxDynamicSharedMemorySize, SMEM);

    // edge dtype detect + convert
    k_detect<<<1, 256>>>((const unsigned int*)ei);
    k_convert<<<(EE + 255) / 256, 256>>>(ei);

    // CSR build
    k_zero_deg<<<(NN + 255) / 256, 256>>>();
    k_hist<<<(EE + 255) / 256, 256>>>();
    k_scan_a<<<NCH, 1024>>>();
    k_scan_b<<<1, 32>>>();
    k_scan_c<<<(NN + 255) / 256, 256>>>();
    k_prep<<<(NN + 255) / 256, 256>>>();
    k_scatter<<<(EE + 255) / 256, 256>>>();

    // hidden layers
    for (int l = 0; l < LL; l++) {
        int first = (l == 0) ? 1 : 0;
        k_agg<<<NN, 128>>>(x, first);
        k_zero_stats<<<1, 128>>>();
        k_gemm<<<(NN + 63) / 64, 256, SMEM>>>(x, first,
                                              Wl + l * DD * DD,
                                              Wr + l * DD * DD,
                                              b + l * DD);
        k_bn_finalize<<<1, 128>>>(gamma + l * DD, beta + l * DD);
        k_bn_apply<<<(NN * (DD / 4) + 255) / 256, 256>>>();
    }

    // output layer (project to scalar, then aggregate scalars)
    k_pq<<<(NN + 3) / 4, 128>>>(Wlo, Wro);
    k_final<<<(NN + 255) / 256, 256>>>(bo, out);
    (void)in_sizes; (void)n_in; (void)out_size;
}

// round 3
// speedup vs baseline: 2.0855x; 2.0855x over previous
#include <cuda_runtime.h>
#include <math.h>

#define NN 100000
#define EE 1600000
#define DD 128
#define LL 3
#define EPSV 1e-5f
#define NCH ((NN + 1023) / 1024)   // scan chunks = 98

// ---------------- scratch (static __device__, no allocation) ----------------
__device__ int   g_is64;
__device__ int   g_src[EE];
__device__ int   g_dst[EE];
__device__ int   g_deg[NN];
__device__ int   g_rowptr[NN + 1];
__device__ int   g_cursor[NN];
__device__ int   g_col[EE];
__device__ int   g_bsum[128];
__device__ int   g_boff[128];
__device__ float g_invdeg[NN];
__device__ float g_h[NN * DD];      // BN output (layer input for l>0)
__device__ float g_mean[NN * DD];   // aggregated neighbor mean
__device__ float g_tmp[NN * DD];    // relu(sage) pre-BN
__device__ float g_sum[DD];
__device__ float g_sumsq[DD];
__device__ float g_scale[DD];
__device__ float g_shift[DD];
__device__ float g_p[NN];
__device__ float g_q[NN];

// ---------------- helpers ----------------
__device__ __forceinline__ unsigned tf32r(float f) {
    unsigned r;
    asm("cvt.rna.tf32.f32 %0, %1;" : "=r"(r) : "f"(f));
    return r;
}

__device__ __forceinline__ void mma_tf32(float* c, const unsigned* a, const unsigned* b) {
    asm volatile(
        "mma.sync.aligned.m16n8k8.row.col.f32.tf32.tf32.f32 "
        "{%0,%1,%2,%3}, {%4,%5,%6,%7}, {%8,%9}, {%0,%1,%2,%3};"
        : "+f"(c[0]), "+f"(c[1]), "+f"(c[2]), "+f"(c[3])
        : "r"(a[0]), "r"(a[1]), "r"(a[2]), "r"(a[3]), "r"(b[0]), "r"(b[1]));
}

// ---------------- dtype detect + edge conversion + degree hist ----------------
__global__ void k_detect(const unsigned int* __restrict__ w) {
    __shared__ int nz;
    if (threadIdx.x == 0) nz = 0;
    __syncthreads();
    if (w[threadIdx.x * 2 + 1] != 0u) atomicOr(&nz, 1);
    __syncthreads();
    if (threadIdx.x == 0) g_is64 = nz ? 0 : 1;
}

__global__ void k_zero_deg() {
    int i = blockIdx.x * blockDim.x + threadIdx.x;
    if (i < NN) g_deg[i] = 0;
}

__global__ void k_convert_hist(const void* __restrict__ ei) {
    int e = blockIdx.x * blockDim.x + threadIdx.x;
    if (e >= EE) return;
    int s, d;
    if (g_is64) {
        const long long* p = (const long long*)ei;
        s = (int)p[e];
        d = (int)p[EE + e];
    } else {
        const int* p = (const int*)ei;
        s = p[e];
        d = p[EE + e];
    }
    s = min(max(s, 0), NN - 1);
    d = min(max(d, 0), NN - 1);
    g_src[e] = s;
    g_dst[e] = d;
    atomicAdd(&g_deg[d], 1);
}

// ---------------- CSR scan ----------------
__global__ void k_scan_a() {
    __shared__ int swarp[32];
    int tid = threadIdx.x;
    int i = blockIdx.x * 1024 + tid;
    int v = (i < NN) ? g_deg[i] : 0;
    int lane = tid & 31, w = tid >> 5;
    int x = v;
    #pragma unroll
    for (int o = 1; o < 32; o <<= 1) {
        int y = __shfl_up_sync(0xffffffffu, x, o);
        if (lane >= o) x += y;
    }
    if (lane == 31) swarp[w] = x;
    __syncthreads();
    if (w == 0) {
        int y = swarp[lane];
        #pragma unroll
        for (int o = 1; o < 32; o <<= 1) {
            int z = __shfl_up_sync(0xffffffffu, y, o);
            if (lane >= o) y += z;
        }
        swarp[lane] = y;
    }
    __syncthreads();
    int add = (w > 0) ? swarp[w - 1] : 0;
    x += add;
    if (i < NN) g_rowptr[i + 1] = x;
    if (tid == 1023) g_bsum[blockIdx.x] = x;
}

__global__ void k_scan_b() {
    if (threadIdx.x == 0) {
        int r = 0;
        for (int b = 0; b < NCH; b++) { g_boff[b] = r; r += g_bsum[b]; }
    }
}

__global__ void k_scan_c() {
    int i = blockIdx.x * blockDim.x + threadIdx.x;
    if (i < NN) {
        g_rowptr[i + 1] += g_boff[i >> 10];
        if (i == 0) g_rowptr[0] = 0;
    }
}

__global__ void k_prep() {
    int i = blockIdx.x * blockDim.x + threadIdx.x;
    if (i < NN) {
        g_cursor[i] = g_rowptr[i];
        int d = g_deg[i];
        g_invdeg[i] = (d > 0) ? (1.0f / (float)d) : 0.0f;
    }
}

__global__ void k_scatter() {
    int e = blockIdx.x * blockDim.x + threadIdx.x;
    if (e < EE) {
        int pos = atomicAdd(&g_cursor[g_dst[e]], 1);
        g_col[pos] = g_src[e];
    }
}

// ---------------- aggregation: warp per node, float4 lanes ----------------
__global__ void __launch_bounds__(256) k_agg(const float* __restrict__ x, int firstLayer) {
    const float* __restrict__ in = firstLayer ? x : g_h;
    int n = blockIdx.x * 8 + (threadIdx.x >> 5);
    if (n >= NN) return;
    int lane = threadIdx.x & 31;
    int s = g_rowptr[n], e = g_rowptr[n + 1];
    float4 acc = make_float4(0.f, 0.f, 0.f, 0.f);
    int j = s;
    for (; j + 3 < e; j += 4) {
        int c0 = g_col[j], c1 = g_col[j + 1], c2 = g_col[j + 2], c3 = g_col[j + 3];
        float4 a = __ldg(&((const float4*)(in + (size_t)c0 * DD))[lane]);
        float4 b = __ldg(&((const float4*)(in + (size_t)c1 * DD))[lane]);
        float4 c = __ldg(&((const float4*)(in + (size_t)c2 * DD))[lane]);
        float4 d = __ldg(&((const float4*)(in + (size_t)c3 * DD))[lane]);
        acc.x += a.x + b.x + c.x + d.x;
        acc.y += a.y + b.y + c.y + d.y;
        acc.z += a.z + b.z + c.z + d.z;
        acc.w += a.w + b.w + c.w + d.w;
    }
    for (; j < e; j++) {
        float4 a = __ldg(&((const float4*)(in + (size_t)g_col[j] * DD))[lane]);
        acc.x += a.x; acc.y += a.y; acc.z += a.z; acc.w += a.w;
    }
    float iv = g_invdeg[n];
    acc.x *= iv; acc.y *= iv; acc.z *= iv; acc.w *= iv;
    ((float4*)(g_mean + (size_t)n * DD))[lane] = acc;
}

// ---------------- stats zero ----------------
__global__ void k_zero_stats() {
    int c = threadIdx.x;
    if (c < DD) { g_sum[c] = 0.0f; g_sumsq[c] = 0.0f; }
}

// ---------------- tf32 tensor-core fused SAGE GEMM -------------------------
// C[128rows x 128cols] = [mean | root] (K=256) @ [Wl ; Wr], + bias, relu,
// BN stat reduction. 256 threads = 8 warps (2 along M x 4 along N).
// Warp tile 64x32. mma.sync m16n8k8 tf32. Smem strides padded (68 / 132
// floats) so all fragment LDS are bank-conflict-free.
#define BK 64
#define SAK 68
#define SWN 132
#define SA_FLOATS (128 * SAK)          // 8704
#define SMEM_MMA ((SA_FLOATS + BK * SWN) * 4)   // 34816 + 33792 = 68608 B

__global__ void __launch_bounds__(256, 2) k_mma(
    const float* __restrict__ x, int firstLayer,
    const float* __restrict__ Wl, const float* __restrict__ Wr,
    const float* __restrict__ bias)
{
    extern __shared__ float sm[];
    float* sA = sm;                  // [128][SAK]
    float* sW = sm + SA_FLOATS;      // [BK][SWN]

    const float* __restrict__ root = firstLayer ? x : g_h;
    int tid = threadIdx.x;
    int wid = tid >> 5;
    int lane = tid & 31;
    int wr = wid >> 2;       // 0..1  (M)
    int wc = wid & 3;        // 0..3  (N)
    int g = lane >> 2;       // 0..7
    int t = lane & 3;        // 0..3
    int rowBase = blockIdx.x * 128;

    float acc[4][4][4];
    #pragma unroll
    for (int mt = 0; mt < 4; mt++)
        #pragma unroll
        for (int nt = 0; nt < 4; nt++)
            #pragma unroll
            for (int q = 0; q < 4; q++) acc[mt][nt][q] = 0.0f;

    #pragma unroll 1
    for (int ck = 0; ck < 4; ck++) {
        if (ck) __syncthreads();
        // stage A chunk: 128 rows x 64 k-cols (2048 float4)
        {
            const float* srcA = (ck < 2) ? g_mean : root;
            int cbase4 = (ck & 1) * 16;
            #pragma unroll
            for (int it = 0; it < 8; it++) {
                int i = tid + it * 256;
                int r = i >> 4, c4 = i & 15;
                int row = rowBase + r;
                float4 v = make_float4(0.f, 0.f, 0.f, 0.f);
                if (row < NN) v = __ldg(&((const float4*)(srcA + (size_t)row * DD))[cbase4 + c4]);
                uint4 o;
                o.x = tf32r(v.x); o.y = tf32r(v.y); o.z = tf32r(v.z); o.w = tf32r(v.w);
                *(uint4*)(sA + r * SAK + c4 * 4) = o;
            }
        }
        // stage W chunk: 64 k-rows x 128 n-cols (2048 float4)
        {
            #pragma unroll
            for (int it = 0; it < 8; it++) {
                int i = tid + it * 256;
                int r = i >> 5, c4 = i & 31;
                int kg = ck * BK + r;
                const float* wsrc = (kg < 128) ? (Wl + (size_t)kg * DD)
                                               : (Wr + (size_t)(kg - 128) * DD);
                float4 v = __ldg(&((const float4*)wsrc)[c4]);
                uint4 o;
                o.x = tf32r(v.x); o.y = tf32r(v.y); o.z = tf32r(v.z); o.w = tf32r(v.w);
                *(uint4*)(sW + r * SWN + c4 * 4) = o;
            }
        }
        __syncthreads();

        #pragma unroll
        for (int kk = 0; kk < BK / 8; kk++) {
            unsigned a[4][4];
            #pragma unroll
            for (int mt = 0; mt < 4; mt++) {
                const float* pa = sA + (wr * 64 + mt * 16 + g) * SAK + kk * 8 + t;
                a[mt][0] = __float_as_uint(pa[0]);
                a[mt][1] = __float_as_uint(pa[8 * SAK]);
                a[mt][2] = __float_as_uint(pa[4]);
                a[mt][3] = __float_as_uint(pa[8 * SAK + 4]);
            }
            unsigned b[4][2];
            #pragma unroll
            for (int nt = 0; nt < 4; nt++) {
                const float* pb = sW + (kk * 8 + t) * SWN + wc * 32 + nt * 8 + g;
                b[nt][0] = __float_as_uint(pb[0]);
                b[nt][1] = __float_as_uint(pb[4 * SWN]);
            }
            #pragma unroll
            for (int mt = 0; mt < 4; mt++)
                #pragma unroll
                for (int nt = 0; nt < 4; nt++)
                    mma_tf32(acc[mt][nt], a[mt], b[nt]);
        }
    }

    // ---- epilogue: bias + relu + store + BN stats ----
    float bs0[4], bs1[4];
    #pragma unroll
    for (int nt = 0; nt < 4; nt++) {
        int cb = wc * 32 + nt * 8 + t * 2;
        bs0[nt] = __ldg(&bias[cb]);
        bs1[nt] = __ldg(&bias[cb + 1]);
    }

    float cs[8], cq[8];
    #pragma unroll
    for (int q = 0; q < 8; q++) { cs[q] = 0.f; cq[q] = 0.f; }

    #pragma unroll
    for (int mt = 0; mt < 4; mt++) {
        int r0 = rowBase + wr * 64 + mt * 16 + g;
        int r1 = r0 + 8;
        #pragma unroll
        for (int nt = 0; nt < 4; nt++) {
            int cb = wc * 32 + nt * 8 + t * 2;
            float v0 = fmaxf(acc[mt][nt][0] + bs0[nt], 0.0f);
            float v1 = fmaxf(acc[mt][nt][1] + bs1[nt], 0.0f);
            float v2 = fmaxf(acc[mt][nt][2] + bs0[nt], 0.0f);
            float v3 = fmaxf(acc[mt][nt][3] + bs1[nt], 0.0f);
            if (r0 < NN) {
                *(float2*)(g_tmp + (size_t)r0 * DD + cb) = make_float2(v0, v1);
                cs[nt * 2] += v0;     cq[nt * 2] += v0 * v0;
                cs[nt * 2 + 1] += v1; cq[nt * 2 + 1] += v1 * v1;
            }
            if (r1 < NN) {
                *(float2*)(g_tmp + (size_t)r1 * DD + cb) = make_float2(v2, v3);
                cs[nt * 2] += v2;     cq[nt * 2] += v2 * v2;
                cs[nt * 2 + 1] += v3; cq[nt * 2 + 1] += v3 * v3;
            }
        }
    }

    __syncthreads();
    if (tid < 256) sm[tid] = 0.0f;
    __syncthreads();
    #pragma unroll
    for (int nt = 0; nt < 4; nt++) {
        int cb = wc * 32 + nt * 8 + t * 2;
        atomicAdd(&sm[cb], cs[nt * 2]);
        atomicAdd(&sm[cb + 1], cs[nt * 2 + 1]);
        atomicAdd(&sm[128 + cb], cq[nt * 2]);
        atomicAdd(&sm[128 + cb + 1], cq[nt * 2 + 1]);
    }
    __syncthreads();
    if (tid < 128) {
        atomicAdd(&g_sum[tid], sm[tid]);
        atomicAdd(&g_sumsq[tid], sm[128 + tid]);
    }
}

// ---------------- BN finalize + apply ----------------
__global__ void k_bn_finalize(const float* __restrict__ gamma,
                              const float* __restrict__ beta) {
    int c = threadIdx.x;
    if (c < DD) {
        float m = g_sum[c] * (1.0f / (float)NN);
        float v = g_sumsq[c] * (1.0f / (float)NN) - m * m;
        v = fmaxf(v, 0.0f);
        float sc = gamma[c] * rsqrtf(v + EPSV);
        g_scale[c] = sc;
        g_shift[c] = beta[c] - m * sc;
    }
}

__global__ void k_bn_apply() {
    int i4 = blockIdx.x * blockDim.x + threadIdx.x;
    if (i4 < NN * (DD / 4)) {
        int c4 = i4 & ((DD / 4) - 1);
        float4 s  = ((const float4*)g_scale)[c4];
        float4 sh = ((const float4*)g_shift)[c4];
        float4 v  = ((const float4*)g_tmp)[i4];
        float4 o;
        o.x = s.x * v.x + sh.x;
        o.y = s.y * v.y + sh.y;
        o.z = s.z * v.z + sh.z;
        o.w = s.w * v.w + sh.w;
        ((float4*)g_h)[i4] = o;
    }
}

// ---------------- output layer ----------------
__global__ void k_pq(const float* __restrict__ wlo, const float* __restrict__ wro) {
    int warp = (blockIdx.x * blockDim.x + threadIdx.x) >> 5;
    int lane = threadIdx.x & 31;
    if (warp >= NN) return;
    float4 hv = ((const float4*)(g_h + (size_t)warp * DD))[lane];
    float4 wl = ((const float4*)wlo)[lane];
    float4 wr = ((const float4*)wro)[lane];
    float p = hv.x * wl.x + hv.y * wl.y + hv.z * wl.z + hv.w * wl.w;
    float q = hv.x * wr.x + hv.y * wr.y + hv.z * wr.z + hv.w * wr.w;
    #pragma unroll
    for (int o = 16; o > 0; o >>= 1) {
        p += __shfl_down_sync(0xffffffffu, p, o);
        q += __shfl_down_sync(0xffffffffu, q, o);
    }
    if (lane == 0) { g_p[warp] = p; g_q[warp] = q; }
}

__global__ void k_final(const float* __restrict__ b_out, float* __restrict__ out) {
    int n = blockIdx.x * blockDim.x + threadIdx.x;
    if (n >= NN) return;
    int s = g_rowptr[n], e = g_rowptr[n + 1];
    float acc = 0.0f;
    for (int j = s; j < e; j++) acc += g_p[g_col[j]];
    float z = acc * g_invdeg[n] + g_q[n] + b_out[0];
    out[n] = 1.0f / (1.0f + expf(-z));
}

// ---------------- host ----------------
extern "C" void kernel_launch(void* const* d_in, const int* in_sizes, int n_in,
                              void* d_out, int out_size) {
    const float* x     = (const float*)d_in[0];
    const void*  ei    = d_in[1];
    const float* Wl    = (const float*)d_in[2];
    const float* Wr    = (const float*)d_in[3];
    const float* b     = (const float*)d_in[4];
    const float* gamma = (const float*)d_in[5];
    const float* beta  = (const float*)d_in[6];
    const float* Wlo   = (const float*)d_in[7];
    const float* Wro   = (const float*)d_in[8];
    const float* bo    = (const float*)d_in[9];
    float* out = (float*)d_out;

    cudaFuncSetAttribute(k_mma, cudaFuncAttributeMaxDynamicSharedMemorySize, SMEM_MMA);

    // edge dtype detect + convert + degree histogram
    k_detect<<<1, 256>>>((const unsigned int*)ei);
    k_zero_deg<<<(NN + 255) / 256, 256>>>();
    k_convert_hist<<<(EE + 255) / 256, 256>>>(ei);

    // CSR build
    k_scan_a<<<NCH, 1024>>>();
    k_scan_b<<<1, 32>>>();
    k_scan_c<<<(NN + 255) / 256, 256>>>();
    k_prep<<<(NN + 255) / 256, 256>>>();
    k_scatter<<<(EE + 255) / 256, 256>>>();

    // hidden layers
    for (int l = 0; l < LL; l++) {
        int first = (l == 0) ? 1 : 0;
        k_agg<<<(NN + 7) / 8, 256>>>(x, first);
        k_zero_stats<<<1, 128>>>();
        k_mma<<<(NN + 127) / 128, 256, SMEM_MMA>>>(x, first,
                                                   Wl + l * DD * DD,
                                                   Wr + l * DD * DD,
                                                   b + l * DD);
        k_bn_finalize<<<1, 128>>>(gamma + l * DD, beta + l * DD);
        k_bn_apply<<<(NN * (DD / 4) + 255) / 256, 256>>>();
    }

    // output layer (project to scalar, then aggregate scalars)
    k_pq<<<(NN + 3) / 4, 128>>>(Wlo, Wro);
    k_final<<<(NN + 255) / 256, 256>>>(bo, out);
    (void)in_sizes; (void)n_in; (void)out_size;
}